// round 2
// baseline (speedup 1.0000x reference)
#include <cuda_runtime.h>
#include <mma.h>
#include <math.h>

using namespace nvcuda;

#define B_   2
#define LQ_  1024
#define LK_  1024
#define D_   1024
#define H_   16
#define DH_  64
#define BH_  (B_ * H_)
#define NEG_BIG (-3.402823466e38f)

#define TF32(x) wmma::__float_to_tf32(x)

// ---------------- scratch (static device globals: allocation-guard safe) ----
__device__ float g_q[B_ * LQ_ * D_];            // 8 MB   projected Q
__device__ float g_k[B_ * LK_ * D_];            // 8 MB   projected K
__device__ float g_v[B_ * LK_ * D_];            // 8 MB   projected V
__device__ float g_att[B_ * LQ_ * D_];          // 8 MB   attn output (concat heads)
__device__ int   g_mask_kind;                   // 0=int32, 1=float32, 2=byte

// ---------------- mask dtype detection -------------------------------------
__global__ void detect_mask_kernel(const unsigned int* m) {
    if (threadIdx.x == 0 && blockIdx.x == 0) {
        int all01 = 1, allf = 1;
        for (int i = 0; i < 512; i++) {
            unsigned v = m[i];
            if (v > 1u) all01 = 0;
            if (v != 0u && v != 0x3F800000u) allf = 0;
        }
        g_mask_kind = all01 ? 0 : (allf ? 1 : 2);
    }
}

__device__ __forceinline__ bool mask_true(const void* m, int kind, int idx) {
    if (kind == 0) return ((const int*)m)[idx] != 0;
    if (kind == 1) return ((const float*)m)[idx] != 0.0f;
    return ((const unsigned char*)m)[idx] != 0;
}

// ---------------- tf32 WMMA GEMM: C[2048,1024] = A @ W^T + bias -------------
// BM=128, BN=128, BK=32, 256 threads (8 warps, 2x4), warp tile 64x32 (4x2 wmma)
__global__ __launch_bounds__(256) void gemm_wmma_nt(
    const float* __restrict__ A, const float* __restrict__ W,
    const float* __restrict__ bias, float* __restrict__ C)
{
    __shared__ float As[128][36];
    __shared__ float Ws[128][36];
    __shared__ float Bs[16][132];

    const int tid = threadIdx.x;
    const int w = tid >> 5;
    const int m0 = blockIdx.y * 128, n0 = blockIdx.x * 128;
    const int wm = w & 1;     // 0..1  -> 64-row half
    const int wn = w >> 1;    // 0..3  -> 32-col quarter

    // bias tile: 16 identical rows of bias[n0..n0+128)
    for (int i = tid; i < 16 * 128; i += 256)
        Bs[i >> 7][i & 127] = bias[n0 + (i & 127)];
    __syncthreads();

    wmma::fragment<wmma::accumulator, 16, 16, 8, float> c[4][2];
    #pragma unroll
    for (int i = 0; i < 4; i++)
        #pragma unroll
        for (int j = 0; j < 2; j++)
            wmma::load_matrix_sync(c[i][j], &Bs[0][wn * 32 + j * 16], 132, wmma::mem_row_major);

    const int lr = tid >> 1;            // 0..127
    const int lc = (tid & 1) * 16;      // 0 or 16

    for (int kt = 0; kt < 1024; kt += 32) {
        __syncthreads();
        #pragma unroll
        for (int u = 0; u < 4; u++) {
            float4 av = *(const float4*)&A[(size_t)(m0 + lr) * 1024 + kt + lc + u * 4];
            As[lr][lc + u*4 + 0] = TF32(av.x); As[lr][lc + u*4 + 1] = TF32(av.y);
            As[lr][lc + u*4 + 2] = TF32(av.z); As[lr][lc + u*4 + 3] = TF32(av.w);
            float4 wv = *(const float4*)&W[(size_t)(n0 + lr) * 1024 + kt + lc + u * 4];
            Ws[lr][lc + u*4 + 0] = TF32(wv.x); Ws[lr][lc + u*4 + 1] = TF32(wv.y);
            Ws[lr][lc + u*4 + 2] = TF32(wv.z); Ws[lr][lc + u*4 + 3] = TF32(wv.w);
        }
        __syncthreads();

        #pragma unroll
        for (int kk = 0; kk < 32; kk += 8) {
            wmma::fragment<wmma::matrix_a, 16, 16, 8, wmma::precision::tf32, wmma::row_major> a[4];
            wmma::fragment<wmma::matrix_b, 16, 16, 8, wmma::precision::tf32, wmma::col_major> bf[2];
            #pragma unroll
            for (int i = 0; i < 4; i++)
                wmma::load_matrix_sync(a[i], &As[wm * 64 + i * 16][kk], 36);
            #pragma unroll
            for (int j = 0; j < 2; j++)
                wmma::load_matrix_sync(bf[j], &Ws[wn * 32 + j * 16][kk], 36);
            #pragma unroll
            for (int i = 0; i < 4; i++)
                #pragma unroll
                for (int j = 0; j < 2; j++)
                    wmma::mma_sync(c[i][j], a[i], bf[j], c[i][j]);
        }
    }

    #pragma unroll
    for (int i = 0; i < 4; i++)
        #pragma unroll
        for (int j = 0; j < 2; j++)
            wmma::store_matrix_sync(
                &C[(size_t)(m0 + wm * 64 + i * 16) * 1024 + n0 + wn * 32 + j * 16],
                c[i][j], 1024, wmma::mem_row_major);
}

// ---------------- fused attention: S=QK^T, softmax(+bias/mask), O=PV --------
// One block: 32 q-rows of one (b,h). Full S row-block [32][1024] in smem.
// 256 threads = 8 warps; warp w owns 16x16 subtile (row (w&1)*16, col (w>>1)*16)
// of every 32x64 panel.
__global__ __launch_bounds__(256) void attn_fused(
    const void* __restrict__ mask, const float* __restrict__ lb)
{
    extern __shared__ float sm[];
    float* Ssm = sm;                    // 32 x 1040
    float* Qs  = sm + 32 * 1040;        // 32 x 72
    float* KVs = Qs + 32 * 72;          // 64 x 72

    const int tid = threadIdx.x;
    const int lane = tid & 31, w = tid >> 5;
    const int q0 = blockIdx.x * 32;
    const int bh = blockIdx.y;
    const int b = bh >> 4, h = bh & 15;
    const int hc = h * DH_;

    const int mr = (w & 1) * 16;    // warp's q-row offset within 32
    const int nc = (w >> 1) * 16;   // warp's col offset within 64

    // load Q tile [32][64]
    for (int i = tid; i < 32 * 64; i += 256) {
        int r = i >> 6, c = i & 63;
        Qs[r * 72 + c] = TF32(g_q[(size_t)(b * LQ_ + q0 + r) * D_ + hc + c]);
    }

    // ---- S = Q K^T  (16 panels of 64 k-cols) ----
    for (int kt = 0; kt < 16; kt++) {
        __syncthreads();
        for (int i = tid; i < 64 * 64; i += 256) {
            int r = i >> 6, c = i & 63;
            KVs[r * 72 + c] = TF32(g_k[(size_t)(b * LK_ + kt * 64 + r) * D_ + hc + c]);
        }
        __syncthreads();

        wmma::fragment<wmma::accumulator, 16, 16, 8, float> s;
        wmma::fill_fragment(s, 0.0f);
        #pragma unroll
        for (int kk = 0; kk < 64; kk += 8) {
            wmma::fragment<wmma::matrix_a, 16, 16, 8, wmma::precision::tf32, wmma::row_major> a;
            wmma::fragment<wmma::matrix_b, 16, 16, 8, wmma::precision::tf32, wmma::col_major> bf;
            wmma::load_matrix_sync(a, &Qs[mr * 72 + kk], 72);
            wmma::load_matrix_sync(bf, &KVs[nc * 72 + kk], 72);
            wmma::mma_sync(s, a, bf, s);
        }
        wmma::store_matrix_sync(&Ssm[mr * 1040 + kt * 64 + nc], s, 1040, wmma::mem_row_major);
    }
    __syncthreads();

    // ---- scale + bias + mask + softmax (each warp: 4 full rows) ----
    const int kind = g_mask_kind;
    for (int rr = 0; rr < 4; rr++) {
        int row = w * 4 + rr;
        int q = q0 + row;
        const float* lbrow = lb + (size_t)(b * LQ_ + q) * LK_;
        float vals[32];
        float mx = NEG_BIG;
        #pragma unroll
        for (int j = 0; j < 32; j++) {
            int k = lane + 32 * j;
            float raw = Ssm[row * 1040 + k];
            bool mk = mask_true(mask, kind, b * LK_ + k);
            float add = mk ? NEG_BIG : lbrow[k];
            float v = fmaf(raw, 0.125f, add);
            vals[j] = v;
            mx = fmaxf(mx, v);
        }
        #pragma unroll
        for (int o = 16; o > 0; o >>= 1) mx = fmaxf(mx, __shfl_xor_sync(0xffffffffu, mx, o));
        float sum = 0.0f;
        #pragma unroll
        for (int j = 0; j < 32; j++) { vals[j] = __expf(vals[j] - mx); sum += vals[j]; }
        #pragma unroll
        for (int o = 16; o > 0; o >>= 1) sum += __shfl_xor_sync(0xffffffffu, sum, o);
        float inv = 1.0f / sum;
        #pragma unroll
        for (int j = 0; j < 32; j++)
            Ssm[row * 1040 + lane + 32 * j] = TF32(vals[j] * inv);
    }

    // ---- O = P V ----
    wmma::fragment<wmma::accumulator, 16, 16, 8, float> oc;
    wmma::fill_fragment(oc, 0.0f);
    for (int kt = 0; kt < 16; kt++) {
        __syncthreads();
        for (int i = tid; i < 64 * 64; i += 256) {
            int r = i >> 6, c = i & 63;
            KVs[r * 72 + c] = TF32(g_v[(size_t)(b * LK_ + kt * 64 + r) * D_ + hc + c]);
        }
        __syncthreads();
        #pragma unroll
        for (int kk = 0; kk < 64; kk += 8) {
            wmma::fragment<wmma::matrix_a, 16, 16, 8, wmma::precision::tf32, wmma::row_major> a;
            wmma::fragment<wmma::matrix_b, 16, 16, 8, wmma::precision::tf32, wmma::row_major> bf;
            wmma::load_matrix_sync(a, &Ssm[mr * 1040 + kt * 64 + kk], 1040);
            wmma::load_matrix_sync(bf, &KVs[kk * 72 + nc], 72);
            wmma::mma_sync(oc, a, bf, oc);
        }
    }
    wmma::store_matrix_sync(&g_att[(size_t)(b * LQ_ + q0 + mr) * D_ + hc + nc],
                            oc, 1024, wmma::mem_row_major);
}

// ---------------- launch ----------------------------------------------------
static const int ATTN_SMEM = (32 * 1040 + 32 * 72 + 64 * 72) * 4;  // 160768 B

extern "C" void kernel_launch(void* const* d_in, const int* in_sizes, int n_in,
                              void* d_out, int out_size)
{
    const float* q    = (const float*)d_in[0];
    const float* k    = (const float*)d_in[1];
    const float* v    = (const float*)d_in[2];
    const float* Wq   = (const float*)d_in[3];
    const float* bq   = (const float*)d_in[4];
    const float* Wk   = (const float*)d_in[5];
    const float* bk   = (const float*)d_in[6];
    const float* Wv   = (const float*)d_in[7];
    const float* bv   = (const float*)d_in[8];
    const float* Wo   = (const float*)d_in[9];
    const float* bo   = (const float*)d_in[10];
    const float* lb   = (const float*)d_in[11];
    const void*  mask = (const void*)d_in[12];
    float* out = (float*)d_out;

    float *pq, *pk, *pv, *patt;
    cudaGetSymbolAddress((void**)&pq,   g_q);
    cudaGetSymbolAddress((void**)&pk,   g_k);
    cudaGetSymbolAddress((void**)&pv,   g_v);
    cudaGetSymbolAddress((void**)&patt, g_att);

    cudaFuncSetAttribute(attn_fused, cudaFuncAttributeMaxDynamicSharedMemorySize, ATTN_SMEM);

    detect_mask_kernel<<<1, 32>>>((const unsigned int*)mask);

    dim3 gproj(8, 16);   // N/128 x (B*LQ)/128
    gemm_wmma_nt<<<gproj, 256>>>(q, Wq, bq, pq);
    gemm_wmma_nt<<<gproj, 256>>>(k, Wk, bk, pk);
    gemm_wmma_nt<<<gproj, 256>>>(v, Wv, bv, pv);

    // q-tile fast, bh slow: concurrent blocks share K/V head in L2
    attn_fused<<<dim3(LQ_ / 32, BH_), 256, ATTN_SMEM>>>(mask, lb);

    gemm_wmma_nt<<<gproj, 256>>>(patt, Wo, bo, out);
}

// round 3
// speedup vs baseline: 2.2952x; 2.2952x over previous
#include <cuda_runtime.h>
#include <mma.h>
#include <math.h>

using namespace nvcuda;

#define B_   2
#define LQ_  1024
#define LK_  1024
#define D_   1024
#define H_   16
#define DH_  64
#define BH_  (B_ * H_)
#define NEG_BIG (-3.402823466e38f)

#define TF32(x) wmma::__float_to_tf32(x)

// ---------------- scratch ----------------------------------------------------
__device__ float g_q[B_ * LQ_ * D_];
__device__ float g_k[B_ * LK_ * D_];
__device__ float g_v[B_ * LK_ * D_];
__device__ float g_s[(size_t)BH_ * LQ_ * LK_];   // 134 MB scores/probs
__device__ float g_att[B_ * LQ_ * D_];
__device__ int   g_mask_kind;

// ---------------- mask dtype detection --------------------------------------
__global__ void detect_mask_kernel(const unsigned int* m) {
    if (threadIdx.x == 0 && blockIdx.x == 0) {
        int all01 = 1, allf = 1;
        for (int i = 0; i < 512; i++) {
            unsigned v = m[i];
            if (v > 1u) all01 = 0;
            if (v != 0u && v != 0x3F800000u) allf = 0;
        }
        g_mask_kind = all01 ? 0 : (allf ? 1 : 2);
    }
}

__device__ __forceinline__ bool mask_true(const void* m, int kind, int idx) {
    if (kind == 0) return ((const int*)m)[idx] != 0;
    if (kind == 1) return ((const float*)m)[idx] != 0.0f;
    return ((const unsigned char*)m)[idx] != 0;
}

// ---------------- tf32 GEMM: C[2048,1024] = A @ W^T + bias ------------------
// BM=128 BN=64 BK=32, 256 thr, 8 warps (4M x 2N), warp 32x32 = 2x2 frags.
// Register-staged global loads overlap MMA.
__global__ __launch_bounds__(256, 2) void gemm_wmma_nt(
    const float* __restrict__ A, const float* __restrict__ W,
    const float* __restrict__ bias, float* __restrict__ C)
{
    __shared__ float As[128][36];
    __shared__ float Ws[64][36];
    __shared__ float Bs[16][68];

    const int tid = threadIdx.x;
    const int w = tid >> 5;
    const int m0 = blockIdx.y * 128, n0 = blockIdx.x * 64;
    const int wm = w >> 1, wn = w & 1;

    for (int i = tid; i < 16 * 64; i += 256)
        Bs[i >> 6][i & 63] = bias[n0 + (i & 63)];
    __syncthreads();

    wmma::fragment<wmma::accumulator, 16, 16, 8, float> c[2][2];
    #pragma unroll
    for (int i = 0; i < 2; i++)
        #pragma unroll
        for (int j = 0; j < 2; j++)
            wmma::load_matrix_sync(c[i][j], &Bs[0][wn * 32 + j * 16], 68, wmma::mem_row_major);

    // load maps: A 128x32 -> 4 float4/thread ; W 64x32 -> 2 float4/thread
    const int ar = tid >> 3, ac = (tid & 7) * 4;       // +32 rows per step
    const int wr = tid >> 3, wc = (tid & 7) * 4;       // first 512 f4 rows 0..63

    float4 ra[4], rw[2];
    #pragma unroll
    for (int u = 0; u < 4; u++)
        ra[u] = *(const float4*)&A[(size_t)(m0 + ar + u * 32) * 1024 + ac];
    #pragma unroll
    for (int u = 0; u < 2; u++)
        rw[u] = *(const float4*)&W[(size_t)(n0 + wr % 64 + u * 32 * 0) * 1024 + wc];
    // simpler W map: idx4 = tid + u*256 ; row = idx4>>3 (0..63), col=(idx4&7)*4
    #pragma unroll
    for (int u = 0; u < 2; u++) {
        int idx = tid + u * 256;
        rw[u] = *(const float4*)&W[(size_t)(n0 + (idx >> 3)) * 1024 + (idx & 7) * 4];
    }

    for (int kt = 0; kt < 1024; kt += 32) {
        #pragma unroll
        for (int u = 0; u < 4; u++)
            *(float4*)&As[ar + u * 32][ac] =
                make_float4(TF32(ra[u].x), TF32(ra[u].y), TF32(ra[u].z), TF32(ra[u].w));
        #pragma unroll
        for (int u = 0; u < 2; u++) {
            int idx = tid + u * 256;
            *(float4*)&Ws[idx >> 3][(idx & 7) * 4] =
                make_float4(TF32(rw[u].x), TF32(rw[u].y), TF32(rw[u].z), TF32(rw[u].w));
        }
        __syncthreads();

        if (kt + 32 < 1024) {
            #pragma unroll
            for (int u = 0; u < 4; u++)
                ra[u] = *(const float4*)&A[(size_t)(m0 + ar + u * 32) * 1024 + kt + 32 + ac];
            #pragma unroll
            for (int u = 0; u < 2; u++) {
                int idx = tid + u * 256;
                rw[u] = *(const float4*)&W[(size_t)(n0 + (idx >> 3)) * 1024 + kt + 32 + (idx & 7) * 4];
            }
        }

        #pragma unroll
        for (int kk = 0; kk < 32; kk += 8) {
            wmma::fragment<wmma::matrix_a, 16, 16, 8, wmma::precision::tf32, wmma::row_major> a[2];
            wmma::fragment<wmma::matrix_b, 16, 16, 8, wmma::precision::tf32, wmma::col_major> bf[2];
            #pragma unroll
            for (int i = 0; i < 2; i++)
                wmma::load_matrix_sync(a[i], &As[wm * 32 + i * 16][kk], 36);
            #pragma unroll
            for (int j = 0; j < 2; j++)
                wmma::load_matrix_sync(bf[j], &Ws[wn * 32 + j * 16][kk], 36);
            #pragma unroll
            for (int i = 0; i < 2; i++)
                #pragma unroll
                for (int j = 0; j < 2; j++)
                    wmma::mma_sync(c[i][j], a[i], bf[j], c[i][j]);
        }
        __syncthreads();
    }

    #pragma unroll
    for (int i = 0; i < 2; i++)
        #pragma unroll
        for (int j = 0; j < 2; j++)
            wmma::store_matrix_sync(
                &C[(size_t)(m0 + wm * 32 + i * 16) * 1024 + n0 + wn * 32 + j * 16],
                c[i][j], 1024, wmma::mem_row_major);
}

// ---------------- scores: S = (Q*scale) Kh^T + bias/mask --------------------
// 128x128 S tile per CTA, 8 warps (2M x 4N), warp 64x32 = 4x2 frags.
__global__ __launch_bounds__(256) void scores_wmma(
    const void* __restrict__ mask, const float* __restrict__ lb)
{
    extern __shared__ float buf[];
    float* Qs = buf;                 // 128 x 72
    float* Ks = buf + 128 * 72;      // 128 x 72
    float* Ss = buf;                 // reused: 128 x 132 (<= 2*128*72)

    const int tid = threadIdx.x;
    const int w = tid >> 5;
    const int k0 = blockIdx.x * 128, q0 = blockIdx.y * 128;
    const int bh = blockIdx.z;
    const int b = bh >> 4, h = bh & 15;
    const int hc = h * DH_;
    const int wm = w >> 2, wn = w & 3;    // 2 x 4

    for (int i = tid * 4; i < 128 * 64; i += 1024) {
        int r = i >> 6, cc = i & 63;
        float4 qv = *(const float4*)&g_q[(size_t)(b * LQ_ + q0 + r) * D_ + hc + cc];
        *(float4*)&Qs[r * 72 + cc] = make_float4(
            TF32(qv.x * 0.125f), TF32(qv.y * 0.125f), TF32(qv.z * 0.125f), TF32(qv.w * 0.125f));
        float4 kv = *(const float4*)&g_k[(size_t)(b * LK_ + k0 + r) * D_ + hc + cc];
        *(float4*)&Ks[r * 72 + cc] = make_float4(TF32(kv.x), TF32(kv.y), TF32(kv.z), TF32(kv.w));
    }
    __syncthreads();

    wmma::fragment<wmma::accumulator, 16, 16, 8, float> s[4][2];
    #pragma unroll
    for (int i = 0; i < 4; i++)
        #pragma unroll
        for (int j = 0; j < 2; j++)
            wmma::fill_fragment(s[i][j], 0.0f);

    #pragma unroll
    for (int kk = 0; kk < 64; kk += 8) {
        wmma::fragment<wmma::matrix_a, 16, 16, 8, wmma::precision::tf32, wmma::row_major> a[4];
        wmma::fragment<wmma::matrix_b, 16, 16, 8, wmma::precision::tf32, wmma::col_major> bf[2];
        #pragma unroll
        for (int i = 0; i < 4; i++)
            wmma::load_matrix_sync(a[i], &Qs[(wm * 64 + i * 16) * 72 + kk], 72);
        #pragma unroll
        for (int j = 0; j < 2; j++)
            wmma::load_matrix_sync(bf[j], &Ks[(wn * 32 + j * 16) * 72 + kk], 72);
        #pragma unroll
        for (int i = 0; i < 4; i++)
            #pragma unroll
            for (int j = 0; j < 2; j++)
                wmma::mma_sync(s[i][j], a[i], bf[j], s[i][j]);
    }
    __syncthreads();   // done with Qs/Ks; reuse as Ss

    #pragma unroll
    for (int i = 0; i < 4; i++)
        #pragma unroll
        for (int j = 0; j < 2; j++)
            wmma::store_matrix_sync(&Ss[(wm * 64 + i * 16) * 132 + wn * 32 + j * 16],
                                    s[i][j], 132, wmma::mem_row_major);
    __syncthreads();

    const int kind = g_mask_kind;
    for (int i = tid * 4; i < 128 * 128; i += 1024) {
        int r = i >> 7, cc = i & 127;
        int q = q0 + r;
        float4 v = *(float4*)&Ss[r * 132 + cc];
        const float* lbrow = lb + (size_t)(b * LQ_ + q) * LK_ + k0 + cc;
        float o[4] = {v.x, v.y, v.z, v.w};
        #pragma unroll
        for (int e = 0; e < 4; e++) {
            bool mk = mask_true(mask, kind, b * LK_ + k0 + cc + e);
            o[e] += mk ? NEG_BIG : lbrow[e];
        }
        *(float4*)&g_s[((size_t)bh * LQ_ + q) * LK_ + k0 + cc] =
            make_float4(o[0], o[1], o[2], o[3]);
    }
}

// ---------------- row softmax over LK=1024 ----------------------------------
__global__ __launch_bounds__(256) void softmax_kernel() {
    const size_t row = blockIdx.x;
    float* s = &g_s[row * LK_];
    const int tid = threadIdx.x;
    const int lane = tid & 31, wid = tid >> 5;

    float4 v = *(float4*)&s[tid * 4];
    float m = fmaxf(fmaxf(v.x, v.y), fmaxf(v.z, v.w));
    #pragma unroll
    for (int o = 16; o > 0; o >>= 1) m = fmaxf(m, __shfl_xor_sync(0xffffffffu, m, o));

    __shared__ float red[8], red2[8];
    if (lane == 0) red[wid] = m;
    __syncthreads();
    float bm = red[0];
    #pragma unroll
    for (int i = 1; i < 8; i++) bm = fmaxf(bm, red[i]);

    float e0 = __expf(v.x - bm), e1 = __expf(v.y - bm);
    float e2 = __expf(v.z - bm), e3 = __expf(v.w - bm);
    float sum = e0 + e1 + e2 + e3;
    #pragma unroll
    for (int o = 16; o > 0; o >>= 1) sum += __shfl_xor_sync(0xffffffffu, sum, o);
    if (lane == 0) red2[wid] = sum;
    __syncthreads();
    float tot = 0.0f;
    #pragma unroll
    for (int i = 0; i < 8; i++) tot += red2[i];

    float inv = 1.0f / tot;
    *(float4*)&s[tid * 4] = make_float4(e0 * inv, e1 * inv, e2 * inv, e3 * inv);
}

// ---------------- PV: att = P @ Vh ------------------------------------------
// BM=128 N=64 BK=32, 256 thr, 8 warps (4M x 2N), warp 32x32, reg-staged.
__global__ __launch_bounds__(256, 2) void pv_wmma() {
    __shared__ float Ps[128][36];
    __shared__ float Vs[32][72];

    const int tid = threadIdx.x;
    const int w = tid >> 5;
    const int m0 = blockIdx.x * 128;
    const int bh = blockIdx.y;
    const int b = bh >> 4, h = bh & 15;
    const int hc = h * DH_;
    const int wm = w >> 1, wn = w & 1;

    const int pr = tid >> 3, pc = (tid & 7) * 4;      // P: +32 rows/step, 4 steps
    // V: idx4 = tid + u*256 ; row = idx4>>4 (0..31), col = (idx4&15)*4

    wmma::fragment<wmma::accumulator, 16, 16, 8, float> c[2][2];
    #pragma unroll
    for (int i = 0; i < 2; i++)
        #pragma unroll
        for (int j = 0; j < 2; j++)
            wmma::fill_fragment(c[i][j], 0.0f);

    float4 rp[4], rv[2];
    #pragma unroll
    for (int u = 0; u < 4; u++)
        rp[u] = *(const float4*)&g_s[((size_t)bh * LQ_ + m0 + pr + u * 32) * LK_ + pc];
    #pragma unroll
    for (int u = 0; u < 2; u++) {
        int idx = tid + u * 256;
        rv[u] = *(const float4*)&g_v[(size_t)(b * LK_ + (idx >> 4)) * D_ + hc + (idx & 15) * 4];
    }

    for (int kt = 0; kt < 1024; kt += 32) {
        #pragma unroll
        for (int u = 0; u < 4; u++)
            *(float4*)&Ps[pr + u * 32][pc] =
                make_float4(TF32(rp[u].x), TF32(rp[u].y), TF32(rp[u].z), TF32(rp[u].w));
        #pragma unroll
        for (int u = 0; u < 2; u++) {
            int idx = tid + u * 256;
            *(float4*)&Vs[idx >> 4][(idx & 15) * 4] =
                make_float4(TF32(rv[u].x), TF32(rv[u].y), TF32(rv[u].z), TF32(rv[u].w));
        }
        __syncthreads();

        if (kt + 32 < 1024) {
            #pragma unroll
            for (int u = 0; u < 4; u++)
                rp[u] = *(const float4*)&g_s[((size_t)bh * LQ_ + m0 + pr + u * 32) * LK_ + kt + 32 + pc];
            #pragma unroll
            for (int u = 0; u < 2; u++) {
                int idx = tid + u * 256;
                rv[u] = *(const float4*)&g_v[(size_t)(b * LK_ + kt + 32 + (idx >> 4)) * D_ + hc + (idx & 15) * 4];
            }
        }

        #pragma unroll
        for (int kk = 0; kk < 32; kk += 8) {
            wmma::fragment<wmma::matrix_a, 16, 16, 8, wmma::precision::tf32, wmma::row_major> a[2];
            wmma::fragment<wmma::matrix_b, 16, 16, 8, wmma::precision::tf32, wmma::row_major> bf[2];
            #pragma unroll
            for (int i = 0; i < 2; i++)
                wmma::load_matrix_sync(a[i], &Ps[wm * 32 + i * 16][kk], 36);
            #pragma unroll
            for (int j = 0; j < 2; j++)
                wmma::load_matrix_sync(bf[j], &Vs[kk][wn * 32 + j * 16], 72);
            #pragma unroll
            for (int i = 0; i < 2; i++)
                #pragma unroll
                for (int j = 0; j < 2; j++)
                    wmma::mma_sync(c[i][j], a[i], bf[j], c[i][j]);
        }
        __syncthreads();
    }

    #pragma unroll
    for (int i = 0; i < 2; i++)
        #pragma unroll
        for (int j = 0; j < 2; j++)
            wmma::store_matrix_sync(
                &g_att[(size_t)(b * LQ_ + m0 + wm * 32 + i * 16) * D_ + hc + wn * 32 + j * 16],
                c[i][j], 1024, wmma::mem_row_major);
}

// ---------------- launch ----------------------------------------------------
static const int SCORES_SMEM = 2 * 128 * 72 * 4;   // 73728 B

extern "C" void kernel_launch(void* const* d_in, const int* in_sizes, int n_in,
                              void* d_out, int out_size)
{
    const float* q    = (const float*)d_in[0];
    const float* k    = (const float*)d_in[1];
    const float* v    = (const float*)d_in[2];
    const float* Wq   = (const float*)d_in[3];
    const float* bq   = (const float*)d_in[4];
    const float* Wk   = (const float*)d_in[5];
    const float* bk   = (const float*)d_in[6];
    const float* Wv   = (const float*)d_in[7];
    const float* bv   = (const float*)d_in[8];
    const float* Wo   = (const float*)d_in[9];
    const float* bo   = (const float*)d_in[10];
    const float* lb   = (const float*)d_in[11];
    const void*  mask = (const void*)d_in[12];
    float* out = (float*)d_out;

    float *pq, *pk, *pv, *patt;
    cudaGetSymbolAddress((void**)&pq,   g_q);
    cudaGetSymbolAddress((void**)&pk,   g_k);
    cudaGetSymbolAddress((void**)&pv,   g_v);
    cudaGetSymbolAddress((void**)&patt, g_att);

    cudaFuncSetAttribute(scores_wmma, cudaFuncAttributeMaxDynamicSharedMemorySize, SCORES_SMEM);

    detect_mask_kernel<<<1, 32>>>((const unsigned int*)mask);

    dim3 gproj(16, 16);   // N/64 x M/128
    gemm_wmma_nt<<<gproj, 256>>>(q, Wq, bq, pq);
    gemm_wmma_nt<<<gproj, 256>>>(k, Wk, bk, pk);
    gemm_wmma_nt<<<gproj, 256>>>(v, Wv, bv, pv);

    scores_wmma<<<dim3(8, 8, BH_), 256, SCORES_SMEM>>>(mask, lb);

    softmax_kernel<<<BH_ * LQ_, 256>>>();

    pv_wmma<<<dim3(8, BH_), 256>>>();

    gemm_wmma_nt<<<gproj, 256>>>(patt, Wo, bo, out);
}